// round 2
// baseline (speedup 1.0000x reference)
#include <cuda_runtime.h>

#define NN 64
#define MM 1728
#define THREADS 256

// ---------------- device scratch (no allocations allowed) ----------------
__device__ float g_keep[NN * MM];
__device__ float g_d[NN * 384];
__device__ float g_pre[NN * 3];

__device__ __forceinline__ float lrelu(float v) { return v > 0.f ? v : 0.01f * v; }

// ---------------- kernel 1: mask + rank scan -> keep, zero g_d ----------------
__global__ void k_prep(const float* __restrict__ x) {
    __shared__ float sx[192];
    __shared__ unsigned char smask[MM];
    int n = blockIdx.x;
    int tid = threadIdx.x;
    if (tid < 192) sx[tid] = x[tid];
    for (int i = tid; i < 384; i += blockDim.x) g_d[n * 384 + i] = 0.f;
    __syncthreads();
    // rel[n][m] = x[j] - x[n] + 10*(a,b,d)  (a,b,d in {0,1,2})
    float xn0 = sx[n * 3 + 0];
    float xn1 = sx[n * 3 + 1];
    float xn2 = sx[n * 3 + 2];
    for (int m = tid; m < MM; m += blockDim.x) {
        int c = m >> 6, j = m & 63;
        int a = c / 9, b = (c / 3) % 3, dd = c % 3;
        float r0 = sx[j * 3 + 0] + 10.f * a - xn0;
        float r1 = sx[j * 3 + 1] + 10.f * b - xn1;
        float r2 = sx[j * 3 + 2] + 10.f * dd - xn2;
        float dist = sqrtf(r0 * r0 + r1 * r1 + r2 * r2);
        smask[m] = (dist <= 25.0f) ? 1 : 0;
    }
    __syncthreads();
    if (tid < 32) {
        int lane = tid;
        int running = 0;
        for (int base = 0; base < MM; base += 32) {
            int v = smask[base + lane];
            int s = v;
            #pragma unroll
            for (int off = 1; off < 32; off <<= 1) {
                int y = __shfl_up_sync(0xffffffffu, s, off);
                if (lane >= off) s += y;
            }
            int rank = running + s - 1;  // inclusive cumsum - 1
            g_keep[n * MM + base + lane] = (v && (rank != n)) ? 1.f : 0.f;
            running += __shfl_sync(0xffffffffu, s, 31);
        }
    }
}

// ---------------- kernel 2: embedding MLP + contraction into g_d ----------------
// smem layout (floats)
#define SW_W1 0
#define SW_B1 288
#define SW_W2 384
#define SW_B2 6528
#define SW_W3 6720
#define SW_B3 31296
#define SW_TOTAL 31680
#define RELK_OFF SW_TOTAL              // 256 * 4 floats
#define SG_OFF (SW_TOTAL + 1024)       // 256 * 36 floats
#define DS_OFF (SG_OFF + 9216)         // 384 floats
#define SMEM_FLOATS (DS_OFF + 384)

__global__ void __launch_bounds__(THREADS, 1)
k_embed(const float* __restrict__ x, const int* __restrict__ at,
        const float* __restrict__ We1, const float* __restrict__ be1,
        const float* __restrict__ We2, const float* __restrict__ be2,
        const float* __restrict__ We3, const float* __restrict__ be3) {
    extern __shared__ float sm[];
    __shared__ float sx[192];
    __shared__ int sat[64];
    int tid = threadIdx.x;
    int n = blockIdx.x;

    // stage all weights into shared (float4 copies)
    {
        const float4* s4;
        float4* d4;
        s4 = (const float4*)We1; d4 = (float4*)(sm + SW_W1);
        for (int i = tid; i < 288 / 4; i += THREADS) d4[i] = s4[i];
        s4 = (const float4*)be1; d4 = (float4*)(sm + SW_B1);
        for (int i = tid; i < 96 / 4; i += THREADS) d4[i] = s4[i];
        s4 = (const float4*)We2; d4 = (float4*)(sm + SW_W2);
        for (int i = tid; i < 6144 / 4; i += THREADS) d4[i] = s4[i];
        s4 = (const float4*)be2; d4 = (float4*)(sm + SW_B2);
        for (int i = tid; i < 192 / 4; i += THREADS) d4[i] = s4[i];
        s4 = (const float4*)We3; d4 = (float4*)(sm + SW_W3);
        for (int i = tid; i < 24576 / 4; i += THREADS) d4[i] = s4[i];
        s4 = (const float4*)be3; d4 = (float4*)(sm + SW_B3);
        for (int i = tid; i < 384 / 4; i += THREADS) d4[i] = s4[i];
    }
    if (tid < 192) sx[tid] = x[tid];
    if (tid < 64) sat[tid] = at[tid];
    for (int i = tid; i < 384; i += THREADS) sm[DS_OFF + i] = 0.f;
    __syncthreads();

    // pair selection: reorder by j-parity so warps are pid-uniform
    int parity = blockIdx.y >> 2;
    int qbase = (blockIdx.y & 3) * 256;
    int t = qbase + tid;
    bool valid = (t < 864);
    int tt = valid ? t : 0;
    int c3 = tt >> 5, jj = tt & 31;
    int j = jj * 2 + parity;
    int m = c3 * 64 + j;
    int a = c3 / 9, b = (c3 / 3) % 3, dd = c3 % 3;
    // rel = x[j] - x[n] + 10*(a,b,d)
    float r0 = sx[j * 3 + 0] + 10.f * a - sx[n * 3 + 0];
    float r1 = sx[j * 3 + 1] + 10.f * b - sx[n * 3 + 1];
    float r2 = sx[j * 3 + 2] + 10.f * dd - sx[n * 3 + 2];
    float keep = valid ? g_keep[n * MM + m] : 0.f;
    int tn = sat[n], tj = sat[j];
    int lo = min(tn, tj), hi = max(tn, tj);
    int pid = lo * 2 - (lo * (lo - 1)) / 2 + (hi - lo);

    // stage keep-premultiplied rel (read later by own warp only)
    ((float4*)(sm + RELK_OFF))[tid] = make_float4(r0 * keep, r1 * keep, r2 * keep, 0.f);

    // ---- layer 1: 3 -> 32 ----
    float h1[32];
    {
        const float* W1 = sm + SW_W1 + pid * 96;
        const float4* B1 = (const float4*)(sm + SW_B1 + pid * 32);
        #pragma unroll
        for (int o4 = 0; o4 < 8; o4++) {
            float4 acc = B1[o4];
            float4 w0 = ((const float4*)(W1 + 0 * 32))[o4];
            float4 w1 = ((const float4*)(W1 + 1 * 32))[o4];
            float4 w2 = ((const float4*)(W1 + 2 * 32))[o4];
            acc.x += r0 * w0.x + r1 * w1.x + r2 * w2.x;
            acc.y += r0 * w0.y + r1 * w1.y + r2 * w2.y;
            acc.z += r0 * w0.z + r1 * w1.z + r2 * w2.z;
            acc.w += r0 * w0.w + r1 * w1.w + r2 * w2.w;
            h1[o4 * 4 + 0] = lrelu(acc.x);
            h1[o4 * 4 + 1] = lrelu(acc.y);
            h1[o4 * 4 + 2] = lrelu(acc.z);
            h1[o4 * 4 + 3] = lrelu(acc.w);
        }
    }

    // ---- layer 2: 32 -> 64 ----
    float h2[64];
    {
        const float* W2 = sm + SW_W2 + pid * 2048;
        const float4* B2 = (const float4*)(sm + SW_B2 + pid * 64);
        #pragma unroll
        for (int o4 = 0; o4 < 16; o4++) {
            float4 acc = B2[o4];
            #pragma unroll
            for (int i = 0; i < 32; i++) {
                float4 w = ((const float4*)(W2 + i * 64))[o4];
                float hv = h1[i];
                acc.x += hv * w.x; acc.y += hv * w.y;
                acc.z += hv * w.z; acc.w += hv * w.w;
            }
            h2[o4 * 4 + 0] = lrelu(acc.x);
            h2[o4 * 4 + 1] = lrelu(acc.y);
            h2[o4 * 4 + 2] = lrelu(acc.z);
            h2[o4 * 4 + 3] = lrelu(acc.w);
        }
    }

    // ---- layer 3: 64 -> 128 in 4 chunks of 32, fused with d contraction ----
    float dacc[4][3];
    #pragma unroll
    for (int k = 0; k < 4; k++) { dacc[k][0] = 0.f; dacc[k][1] = 0.f; dacc[k][2] = 0.f; }

    int warp = tid >> 5, lane = tid & 31;
    const float* W3 = sm + SW_W3 + pid * 8192;
    const float4* B3 = (const float4*)(sm + SW_B3 + pid * 128);
    float* myrow = sm + SG_OFF + tid * 36;
    const float* wrows = sm + SG_OFF + (warp * 32) * 36;
    const float4* relkw = ((const float4*)(sm + RELK_OFF)) + warp * 32;

    #pragma unroll
    for (int k = 0; k < 4; k++) {
        for (int o4 = 0; o4 < 8; o4++) {
            float4 acc = B3[k * 8 + o4];
            #pragma unroll
            for (int i = 0; i < 64; i++) {
                float4 w = ((const float4*)(W3 + i * 128))[k * 8 + o4];
                float hv = h2[i];
                acc.x += hv * w.x; acc.y += hv * w.y;
                acc.z += hv * w.z; acc.w += hv * w.w;
            }
            ((float4*)myrow)[o4] = make_float4(lrelu(acc.x), lrelu(acc.y),
                                               lrelu(acc.z), lrelu(acc.w));
        }
        __syncwarp();
        // warp-local transpose reduce: lane owns output o = k*32 + lane
        #pragma unroll 4
        for (int qq = 0; qq < 32; qq++) {
            float gv = wrows[qq * 36 + lane];
            float4 rk = relkw[qq];
            dacc[k][0] += gv * rk.x;
            dacc[k][1] += gv * rk.y;
            dacc[k][2] += gv * rk.z;
        }
        __syncwarp();
    }

    // block-level reduce then one global atomic pass
    #pragma unroll
    for (int k = 0; k < 4; k++) {
        int o = k * 32 + lane;
        atomicAdd(&sm[DS_OFF + o * 3 + 0], dacc[k][0]);
        atomicAdd(&sm[DS_OFF + o * 3 + 1], dacc[k][1]);
        atomicAdd(&sm[DS_OFF + o * 3 + 2], dacc[k][2]);
    }
    __syncthreads();
    for (int i = tid; i < 384; i += THREADS)
        atomicAdd(&g_d[n * 384 + i], sm[DS_OFF + i]);
}

// ---------------- kernel 3: per-atom fit network ----------------
__global__ void k_fit(const float* __restrict__ Wl1, const float* __restrict__ bl1,
                      const float* __restrict__ Wl2, const float* __restrict__ bl2,
                      const float* __restrict__ Wl3, const float* __restrict__ bl3,
                      const float* __restrict__ Wl4, const float* __restrict__ bl4) {
    __shared__ float b0[384], b1[256];
    int n = blockIdx.x, tid = threadIdx.x;
    for (int i = tid; i < 384; i += 256) b0[i] = g_d[n * 384 + i];
    __syncthreads();
    {
        const float* W = Wl1 + (size_t)n * 384 * 256;
        float acc = bl1[n * 256 + tid];
        #pragma unroll 16
        for (int i = 0; i < 384; i++) acc += b0[i] * W[i * 256 + tid];
        b1[tid] = lrelu(acc);
    }
    __syncthreads();
    {
        const float* W = Wl2 + (size_t)n * 256 * 256;
        float acc = bl2[n * 256 + tid];
        #pragma unroll 16
        for (int i = 0; i < 256; i++) acc += b1[i] * W[i * 256 + tid];
        __syncthreads();          // b1 fully consumed before b0 overwrite
        b0[tid] = lrelu(acc);
    }
    __syncthreads();
    if (tid < 128) {
        const float* W = Wl3 + (size_t)n * 256 * 128;
        float acc = bl3[n * 128 + tid];
        #pragma unroll 16
        for (int i = 0; i < 256; i++) acc += b0[i] * W[i * 128 + tid];
        b1[tid] = lrelu(acc);
    }
    __syncthreads();
    int warp = tid >> 5, lane = tid & 31;
    if (warp < 3) {
        const float* W = Wl4 + (size_t)n * 128 * 3;
        float p = 0.f;
        #pragma unroll
        for (int i = lane; i < 128; i += 32) p += b1[i] * W[i * 3 + warp];
        #pragma unroll
        for (int off = 16; off; off >>= 1) p += __shfl_xor_sync(0xffffffffu, p, off);
        if (lane == 0) g_pre[n * 3 + warp] = p + bl4[n * 3 + warp];
    }
}

// ---------------- kernel 4: mean-subtract -> output ----------------
__global__ void k_mean(float* __restrict__ out) {
    __shared__ float s[192];
    __shared__ float mean[3];
    int tid = threadIdx.x;
    s[tid] = g_pre[tid];
    __syncthreads();
    if (tid < 3) {
        float msum = 0.f;
        #pragma unroll
        for (int i = 0; i < 64; i++) msum += s[i * 3 + tid];
        mean[tid] = msum * (1.f / 64.f);
    }
    __syncthreads();
    out[tid] = s[tid] - mean[tid % 3];
}

// ---------------- launch ----------------
extern "C" void kernel_launch(void* const* d_in, const int* in_sizes, int n_in,
                              void* d_out, int out_size) {
    const float* x   = (const float*)d_in[0];
    const float* We1 = (const float*)d_in[2];
    const float* be1 = (const float*)d_in[3];
    const float* We2 = (const float*)d_in[4];
    const float* be2 = (const float*)d_in[5];
    const float* We3 = (const float*)d_in[6];
    const float* be3 = (const float*)d_in[7];
    const float* Wl1 = (const float*)d_in[8];
    const float* bl1 = (const float*)d_in[9];
    const float* Wl2 = (const float*)d_in[10];
    const float* bl2 = (const float*)d_in[11];
    const float* Wl3 = (const float*)d_in[12];
    const float* bl3 = (const float*)d_in[13];
    const float* Wl4 = (const float*)d_in[14];
    const float* bl4 = (const float*)d_in[15];
    const int*   at  = (const int*)d_in[16];
    float* out = (float*)d_out;

    cudaFuncSetAttribute(k_embed, cudaFuncAttributeMaxDynamicSharedMemorySize,
                         SMEM_FLOATS * (int)sizeof(float));

    k_prep<<<NN, 256>>>(x);
    k_embed<<<dim3(NN, 8), THREADS, SMEM_FLOATS * (int)sizeof(float)>>>(
        x, at, We1, be1, We2, be2, We3, be3);
    k_fit<<<NN, 256>>>(Wl1, bl1, Wl2, bl2, Wl3, bl3, Wl4, bl4);
    k_mean<<<1, 192>>>(out);
}

// round 4
// speedup vs baseline: 1.3759x; 1.3759x over previous
#include <cuda_runtime.h>

#define NN 64
#define MM 1728
#define THREADS 256
#define GRID_EMBED 148
#define WARPS_TOTAL (GRID_EMBED * 8)
#define NTILES 3456   // 64 n * 2 parity * 27 c3

// ---------------- device scratch (no allocations allowed) ----------------
__device__ float g_keep[NN * MM];
__device__ float g_d[NN * 384];
__device__ float g_pre[NN * 3];

__device__ __forceinline__ float lrelu(float v) { return v > 0.f ? v : 0.01f * v; }

// -------- packed f32x2 helpers --------
__device__ __forceinline__ unsigned long long pack2(float v) {
    unsigned long long r;
    asm("mov.b64 %0, {%1, %1};" : "=l"(r) : "r"(__float_as_uint(v)));
    return r;
}
__device__ __forceinline__ void ffma2(unsigned long long& acc, unsigned long long a,
                                      unsigned long long b) {
    asm("fma.rn.f32x2 %0, %1, %2, %0;" : "+l"(acc) : "l"(a), "l"(b));
}
__device__ __forceinline__ void unpack2(unsigned long long v, float& a, float& b) {
    unsigned int lo, hi;
    asm("mov.b64 {%0, %1}, %2;" : "=r"(lo), "=r"(hi) : "l"(v));
    a = __uint_as_float(lo);
    b = __uint_as_float(hi);
}

// ---------------- kernel 1: mask + rank scan -> keep, zero g_d ----------------
__global__ void k_prep(const float* __restrict__ x) {
    __shared__ float sx[192];
    __shared__ unsigned char smask[MM];
    int n = blockIdx.x;
    int tid = threadIdx.x;
    if (tid < 192) sx[tid] = x[tid];
    for (int i = tid; i < 384; i += blockDim.x) g_d[n * 384 + i] = 0.f;
    __syncthreads();
    float xn0 = sx[n * 3 + 0];
    float xn1 = sx[n * 3 + 1];
    float xn2 = sx[n * 3 + 2];
    for (int m = tid; m < MM; m += blockDim.x) {
        int c = m >> 6, j = m & 63;
        int a = c / 9, b = (c / 3) % 3, dd = c % 3;
        float r0 = sx[j * 3 + 0] + 10.f * a - xn0;
        float r1 = sx[j * 3 + 1] + 10.f * b - xn1;
        float r2 = sx[j * 3 + 2] + 10.f * dd - xn2;
        float dist = sqrtf(r0 * r0 + r1 * r1 + r2 * r2);
        smask[m] = (dist <= 25.0f) ? 1 : 0;
    }
    __syncthreads();
    if (tid < 32) {
        int lane = tid;
        int running = 0;
        for (int base = 0; base < MM; base += 32) {
            int v = smask[base + lane];
            int s = v;
            #pragma unroll
            for (int off = 1; off < 32; off <<= 1) {
                int y = __shfl_up_sync(0xffffffffu, s, off);
                if (lane >= off) s += y;
            }
            int rank = running + s - 1;
            g_keep[n * MM + base + lane] = (v && (rank != n)) ? 1.f : 0.f;
            running += __shfl_sync(0xffffffffu, s, 31);
        }
    }
}

// ---------------- kernel 2: persistent embedding MLP + contraction ----------------
// smem layout (floats)
#define SW_W1 0
#define SW_B1 288
#define SW_W2 384
#define SW_B2 6528
#define SW_W3 6720
#define SW_B3 31296
#define SW_TOTAL 31680
#define RELK_OFF SW_TOTAL                 // 8 warps * 32 * 4
#define SG_OFF (RELK_OFF + 1024)          // 8 warps * 32 * 36
#define SMEM_FLOATS (SG_OFF + 9216)       // 41920 floats = 167680 B

__global__ void __launch_bounds__(THREADS, 1)
k_embed(const float* __restrict__ x, const int* __restrict__ at,
        const float* __restrict__ We1, const float* __restrict__ be1,
        const float* __restrict__ We2, const float* __restrict__ be2,
        const float* __restrict__ We3, const float* __restrict__ be3) {
    extern __shared__ float sm[];
    __shared__ float sx[192];
    __shared__ int sat[64];
    int tid = threadIdx.x;
    int warp = tid >> 5, lane = tid & 31;

    // stage all embedding weights into shared once
    {
        const float4* s4;
        float4* d4;
        s4 = (const float4*)We1; d4 = (float4*)(sm + SW_W1);
        for (int i = tid; i < 288 / 4; i += THREADS) d4[i] = s4[i];
        s4 = (const float4*)be1; d4 = (float4*)(sm + SW_B1);
        for (int i = tid; i < 96 / 4; i += THREADS) d4[i] = s4[i];
        s4 = (const float4*)We2; d4 = (float4*)(sm + SW_W2);
        for (int i = tid; i < 6144 / 4; i += THREADS) d4[i] = s4[i];
        s4 = (const float4*)be2; d4 = (float4*)(sm + SW_B2);
        for (int i = tid; i < 192 / 4; i += THREADS) d4[i] = s4[i];
        s4 = (const float4*)We3; d4 = (float4*)(sm + SW_W3);
        for (int i = tid; i < 24576 / 4; i += THREADS) d4[i] = s4[i];
        s4 = (const float4*)be3; d4 = (float4*)(sm + SW_B3);
        for (int i = tid; i < 384 / 4; i += THREADS) d4[i] = s4[i];
    }
    if (tid < 192) sx[tid] = x[tid];
    if (tid < 64) sat[tid] = at[tid];
    __syncthreads();

    float* relkW = sm + RELK_OFF + warp * 128;   // 32 lanes * float4
    float* sgW = sm + SG_OFF + warp * 1152;      // 32 rows * 36
    float* myrow = sgW + lane * 36;

    int gw = blockIdx.x * 8 + warp;

    for (int wt = gw; wt < NTILES; wt += WARPS_TOTAL) {
        int n = wt / 54;
        int rem = wt - n * 54;
        int parity = rem / 27;
        int c3 = rem - parity * 27;
        int j = lane * 2 + parity;
        int m = c3 * 64 + j;
        int a = c3 / 9, b = (c3 / 3) % 3, dd = c3 % 3;
        // rel = x[j] - x[n] + 10*(a,b,d)
        float r0 = sx[j * 3 + 0] + 10.f * a - sx[n * 3 + 0];
        float r1 = sx[j * 3 + 1] + 10.f * b - sx[n * 3 + 1];
        float r2 = sx[j * 3 + 2] + 10.f * dd - sx[n * 3 + 2];
        float keep = g_keep[n * MM + m];
        int tn = sat[n], tj = sat[j];
        int lo = min(tn, tj), hi = max(tn, tj);
        int pid = lo * 2 - (lo * (lo - 1)) / 2 + (hi - lo);

        ((float4*)relkW)[lane] = make_float4(r0 * keep, r1 * keep, r2 * keep, 0.f);

        // ---- layer 1: 3 -> 32 (scalar, tiny) ----
        float h1[32];
        {
            const float* W1 = sm + SW_W1 + pid * 96;
            const float4* B1 = (const float4*)(sm + SW_B1 + pid * 32);
            #pragma unroll
            for (int o4 = 0; o4 < 8; o4++) {
                float4 acc = B1[o4];
                float4 w0 = ((const float4*)(W1 + 0 * 32))[o4];
                float4 w1 = ((const float4*)(W1 + 1 * 32))[o4];
                float4 w2 = ((const float4*)(W1 + 2 * 32))[o4];
                acc.x += r0 * w0.x + r1 * w1.x + r2 * w2.x;
                acc.y += r0 * w0.y + r1 * w1.y + r2 * w2.y;
                acc.z += r0 * w0.z + r1 * w1.z + r2 * w2.z;
                acc.w += r0 * w0.w + r1 * w1.w + r2 * w2.w;
                h1[o4 * 4 + 0] = lrelu(acc.x);
                h1[o4 * 4 + 1] = lrelu(acc.y);
                h1[o4 * 4 + 2] = lrelu(acc.z);
                h1[o4 * 4 + 3] = lrelu(acc.w);
            }
        }

        // ---- layer 2: 32 -> 64, packed f32x2 ----
        float h2[64];
        {
            unsigned long long acc2[32];
            const ulonglong2* B2v = (const ulonglong2*)(sm + SW_B2 + pid * 64);
            #pragma unroll
            for (int o4 = 0; o4 < 16; o4++) {
                ulonglong2 bb = B2v[o4];
                acc2[2 * o4] = bb.x;
                acc2[2 * o4 + 1] = bb.y;
            }
            const ulonglong2* W2v = (const ulonglong2*)(sm + SW_W2 + pid * 2048);
            #pragma unroll
            for (int i = 0; i < 32; i++) {
                unsigned long long hp = pack2(h1[i]);
                const ulonglong2* wrow = W2v + i * 16;
                #pragma unroll
                for (int o4 = 0; o4 < 16; o4++) {
                    ulonglong2 w = wrow[o4];
                    ffma2(acc2[2 * o4], hp, w.x);
                    ffma2(acc2[2 * o4 + 1], hp, w.y);
                }
            }
            #pragma unroll
            for (int p = 0; p < 32; p++) {
                float va, vb;
                unpack2(acc2[p], va, vb);
                h2[2 * p] = lrelu(va);
                h2[2 * p + 1] = lrelu(vb);
            }
        }

        // ---- layer 3: 64 -> 128 in 4 chunks of 32, packed, fused contraction ----
        const ulonglong2* W3v = (const ulonglong2*)(sm + SW_W3 + pid * 8192);
        const ulonglong2* B3v = (const ulonglong2*)(sm + SW_B3 + pid * 128);
        #pragma unroll 1
        for (int k = 0; k < 4; k++) {
            unsigned long long acc3[16];
            #pragma unroll
            for (int o4 = 0; o4 < 8; o4++) {
                ulonglong2 bb = B3v[k * 8 + o4];
                acc3[2 * o4] = bb.x;
                acc3[2 * o4 + 1] = bb.y;
            }
            #pragma unroll
            for (int i = 0; i < 64; i++) {
                unsigned long long hp = pack2(h2[i]);
                const ulonglong2* wrow = W3v + i * 32 + k * 8;
                #pragma unroll
                for (int o4 = 0; o4 < 8; o4++) {
                    ulonglong2 w = wrow[o4];
                    ffma2(acc3[2 * o4], hp, w.x);
                    ffma2(acc3[2 * o4 + 1], hp, w.y);
                }
            }
            #pragma unroll
            for (int o4 = 0; o4 < 8; o4++) {
                float a0, a1, a2, a3;
                unpack2(acc3[2 * o4], a0, a1);
                unpack2(acc3[2 * o4 + 1], a2, a3);
                ((float4*)myrow)[o4] =
                    make_float4(lrelu(a0), lrelu(a1), lrelu(a2), lrelu(a3));
            }
            __syncwarp();
            // warp-local transpose reduce: lane owns output o = k*32 + lane
            float d0 = 0.f, d1 = 0.f, d2 = 0.f;
            #pragma unroll 8
            for (int q = 0; q < 32; q++) {
                float gv = sgW[q * 36 + lane];
                float4 rk = ((const float4*)relkW)[q];
                d0 += gv * rk.x;
                d1 += gv * rk.y;
                d2 += gv * rk.z;
            }
            __syncwarp();
            int o = k * 32 + lane;
            atomicAdd(&g_d[n * 384 + o * 3 + 0], d0);
            atomicAdd(&g_d[n * 384 + o * 3 + 1], d1);
            atomicAdd(&g_d[n * 384 + o * 3 + 2], d2);
        }
        __syncwarp();
    }
}

// ---------------- kernel 3: per-atom fit network ----------------
__global__ void k_fit(const float* __restrict__ Wl1, const float* __restrict__ bl1,
                      const float* __restrict__ Wl2, const float* __restrict__ bl2,
                      const float* __restrict__ Wl3, const float* __restrict__ bl3,
                      const float* __restrict__ Wl4, const float* __restrict__ bl4) {
    __shared__ float b0[384], b1[256];
    int n = blockIdx.x, tid = threadIdx.x;
    for (int i = tid; i < 384; i += 256) b0[i] = g_d[n * 384 + i];
    __syncthreads();
    {
        const float* W = Wl1 + (size_t)n * 384 * 256;
        float acc = bl1[n * 256 + tid];
        #pragma unroll 16
        for (int i = 0; i < 384; i++) acc += b0[i] * W[i * 256 + tid];
        b1[tid] = lrelu(acc);
    }
    __syncthreads();
    {
        const float* W = Wl2 + (size_t)n * 256 * 256;
        float acc = bl2[n * 256 + tid];
        #pragma unroll 16
        for (int i = 0; i < 256; i++) acc += b1[i] * W[i * 256 + tid];
        __syncthreads();
        b0[tid] = lrelu(acc);
    }
    __syncthreads();
    if (tid < 128) {
        const float* W = Wl3 + (size_t)n * 256 * 128;
        float acc = bl3[n * 128 + tid];
        #pragma unroll 16
        for (int i = 0; i < 256; i++) acc += b0[i] * W[i * 128 + tid];
        b1[tid] = lrelu(acc);
    }
    __syncthreads();
    int warp = tid >> 5, lane = tid & 31;
    if (warp < 3) {
        const float* W = Wl4 + (size_t)n * 128 * 3;
        float p = 0.f;
        #pragma unroll
        for (int i = lane; i < 128; i += 32) p += b1[i] * W[i * 3 + warp];
        #pragma unroll
        for (int off = 16; off; off >>= 1) p += __shfl_xor_sync(0xffffffffu, p, off);
        if (lane == 0) g_pre[n * 3 + warp] = p + bl4[n * 3 + warp];
    }
}

// ---------------- kernel 4: mean-subtract -> output ----------------
__global__ void k_mean(float* __restrict__ out) {
    __shared__ float s[192];
    __shared__ float mean[3];
    int tid = threadIdx.x;
    s[tid] = g_pre[tid];
    __syncthreads();
    if (tid < 3) {
        float msum = 0.f;
        #pragma unroll
        for (int i = 0; i < 64; i++) msum += s[i * 3 + tid];
        mean[tid] = msum * (1.f / 64.f);
    }
    __syncthreads();
    out[tid] = s[tid] - mean[tid % 3];
}

// ---------------- launch ----------------
extern "C" void kernel_launch(void* const* d_in, const int* in_sizes, int n_in,
                              void* d_out, int out_size) {
    const float* x   = (const float*)d_in[0];
    const float* We1 = (const float*)d_in[2];
    const float* be1 = (const float*)d_in[3];
    const float* We2 = (const float*)d_in[4];
    const float* be2 = (const float*)d_in[5];
    const float* We3 = (const float*)d_in[6];
    const float* be3 = (const float*)d_in[7];
    const float* Wl1 = (const float*)d_in[8];
    const float* bl1 = (const float*)d_in[9];
    const float* Wl2 = (const float*)d_in[10];
    const float* bl2 = (const float*)d_in[11];
    const float* Wl3 = (const float*)d_in[12];
    const float* bl3 = (const float*)d_in[13];
    const float* Wl4 = (const float*)d_in[14];
    const float* bl4 = (const float*)d_in[15];
    const int*   at  = (const int*)d_in[16];
    float* out = (float*)d_out;

    cudaFuncSetAttribute(k_embed, cudaFuncAttributeMaxDynamicSharedMemorySize,
                         SMEM_FLOATS * (int)sizeof(float));

    k_prep<<<NN, 256>>>(x);
    k_embed<<<GRID_EMBED, THREADS, SMEM_FLOATS * (int)sizeof(float)>>>(
        x, at, We1, be1, We2, be2, We3, be3);
    k_fit<<<NN, 256>>>(Wl1, bl1, Wl2, bl2, Wl3, bl3, Wl4, bl4);
    k_mean<<<1, 192>>>(out);
}